// round 11
// baseline (speedup 1.0000x reference)
#include <cuda_runtime.h>
#include <cuda_bf16.h>
#include <cstdint>

// ---------------------------------------------------------------------------
// BVP Helmholtz residual via 2nd-order jet propagation on mma.sync bf16 HMMA
// (3-pass hi/lo split). Round 11: BARRIER-FREE mainloop — B fragments loaded
// directly from global (L1-resident) into the exact mma register layout, so
// cp.async, B smem and all mainloop barriers disappear. CTA split into two
// independent 256-thread halves (samples 0-11 -> A rows 0..59, samples 12-23
// -> rows 64..123); all epilogue syncs are per-half named barriers. Only the
// coord load and the final output use full __syncthreads.
// ---------------------------------------------------------------------------

#define HD 256
#define SB 24          // samples per CTA (12 per half)
#define AROW 1040      // A row bytes: hi[0,512) pad lo[528,1040) == D row
#define DROW 260       // D row stride in floats (= 1040 B)

#define A_OFF 0
#define XYZF_OFF 133120
#define PART_OFF 133504
#define SMEM_BYTES 136576

// prepped weights: [layer][split hi/lo][n][k] bf16
__device__ __align__(16) __nv_bfloat16 Wbf[2][2][HD][HD];

__global__ __launch_bounds__(256)
void prep_weights(const float* __restrict__ W2, const float* __restrict__ W3)
{
    int t = blockIdx.x * 256 + threadIdx.x;      // 131072
    int layer = t >> 16, n = (t >> 8) & 255, k = t & 255;
    float w = (layer ? W3 : W2)[n * HD + k];
    __nv_bfloat16 h = __float2bfloat16(w);
    __nv_bfloat16 l = __float2bfloat16(w - __bfloat162float(h));
    Wbf[layer][0][n][k] = h;
    Wbf[layer][1][n][k] = l;
}

__device__ __forceinline__ uint32_t smem_u32(const void* p) {
    uint32_t a;
    asm("{ .reg .u64 t; cvta.to.shared.u64 t, %1; cvt.u32.u64 %0, t; }"
        : "=r"(a) : "l"(p));
    return a;
}
__device__ __forceinline__ void ldsm4(uint32_t* r, uint32_t a) {
    asm volatile("ldmatrix.sync.aligned.m8n8.x4.shared.b16 {%0,%1,%2,%3}, [%4];"
                 : "=r"(r[0]), "=r"(r[1]), "=r"(r[2]), "=r"(r[3]) : "r"(a));
}
__device__ __forceinline__ void mma_bf16(float* c, const uint32_t* a,
                                         const uint32_t* b) {
    asm volatile("mma.sync.aligned.m16n8k16.row.col.f32.bf16.bf16.f32 "
                 "{%0,%1,%2,%3}, {%4,%5,%6,%7}, {%8,%9}, {%0,%1,%2,%3};"
                 : "+f"(c[0]), "+f"(c[1]), "+f"(c[2]), "+f"(c[3])
                 : "r"(a[0]), "r"(a[1]), "r"(a[2]), "r"(a[3]),
                   "r"(b[0]), "r"(b[1]));
}
// per-half named barrier (256 threads each); ids 1,2
#define HBAR(h) asm volatile("bar.sync %0, 256;" :: "r"((h) + 1) : "memory")

// fast tanh: 1 - 2/(exp(2u)+1). abs err ~3e-7.
__device__ __forceinline__ float ftanh(float u) {
    float e = __expf(2.0f * u);
    return 1.0f - __fdividef(2.0f, e + 1.0f);
}

__global__ __launch_bounds__(512, 1)
void bvp_mma_kernel(const float* __restrict__ gx, const float* __restrict__ gy,
                    const float* __restrict__ gz, const float* __restrict__ gf,
                    const float* __restrict__ W1, const float* __restrict__ b1,
                    const float* __restrict__ b2, const float* __restrict__ b3,
                    const float* __restrict__ W4, const float* __restrict__ b4,
                    float* __restrict__ out, int N)
{
    extern __shared__ char sm[];
    const uint32_t smb = smem_u32(sm);
    float* Dst  = (float*)(sm + A_OFF);       // aliases A region, row-for-row
    float* xyzf = (float*)(sm + XYZF_OFF);
    float* part = (float*)(sm + PART_OFF);    // [24][8][4]

    const int tid = threadIdx.x;
    const int wid = tid >> 5;
    const int lid = tid & 31;
    const int mg  = wid >> 3;                 // m-group / half (rows mg*64..)
    const int ng  = wid & 7;                  // n-slice (cols ng*32..+32)
    const int n0w = ng << 5;
    const int n0  = blockIdx.x * SB;
    const int hh  = tid >> 8;                 // == mg
    const int nn  = tid & 255;

    const float CX = (float)((0.5 * 0.6) * (0.5 * 0.6));
    const float CY = (float)((0.7 * 0.6) * (0.7 * 0.6));
    const float CZ = (float)((0.7 * 0.5) * (0.7 * 0.5));

    auto storeA = [&](int m, int k, float v) {
        __nv_bfloat16 h = __float2bfloat16(v);
        __nv_bfloat16 l = __float2bfloat16(v - __bfloat162float(h));
        char* base = sm + A_OFF + m * AROW + k * 2;
        *(__nv_bfloat16*)(base)       = h;
        *(__nv_bfloat16*)(base + 528) = l;
    };

    // coords (full CTA, one full sync)
    if (tid < 96) {
        int ss = tid >> 2, w = tid & 3;
        int n = n0 + ss; if (n >= N) n = N - 1;
        const float* p = (w == 0) ? gx : (w == 1) ? gy : (w == 2) ? gz : gf;
        xyzf[tid] = p[n];
    }
    __syncthreads();

    // ---- layer 1: 4 -> 256, jets analytically (half-local) -----------------
    {
        float4 w = *(const float4*)(W1 + nn * 4);
        float bb = b1[nn];
        float g  = CX * w.x * w.x + CY * w.y * w.y + CZ * w.z * w.z;
        #pragma unroll 1
        for (int sl = 0; sl < 12; ++sl) {
            int s = hh * 12 + sl;
            float u = fmaf(w.x, xyzf[s * 4 + 0], fmaf(w.y, xyzf[s * 4 + 1],
                      fmaf(w.z, xyzf[s * 4 + 2], fmaf(w.w, xyzf[s * 4 + 3],
                      bb))));
            float yv = ftanh(u);
            float sg = fmaf(-yv, yv, 1.0f);
            int m = hh * 64 + sl * 5;
            storeA(m + 0, nn, yv);
            storeA(m + 1, nn, sg * w.x);
            storeA(m + 2, nn, sg * w.y);
            storeA(m + 3, nn, sg * w.z);
            storeA(m + 4, nn, -2.0f * yv * sg * g);
        }
    }
    HBAR(hh);

    const int g = lid >> 2, cc = (lid & 3) << 1;

    // ---- hidden layers 2,3 (barrier-free mainloop) --------------------------
    #pragma unroll 1
    for (int L = 0; L < 2; ++L) {
        // per-thread B base: fragment reg (split,nt,t,which) lives at
        // Wbf[L][split][n0w + nt*8 + (lid>>2)][t*16 + (lid&3)*2 + which*8]
        const __nv_bfloat16* pb = &Wbf[L][0][0][0] +
                                  (n0w + (lid >> 2)) * HD + (lid & 3) * 2;

        float acc[4][4][4];
        #pragma unroll
        for (int mt = 0; mt < 4; ++mt)
            #pragma unroll
            for (int nt = 0; nt < 4; ++nt)
                #pragma unroll
                for (int r = 0; r < 4; ++r) acc[mt][nt][r] = 0.f;

        #pragma unroll 2
        for (int t = 0; t < 16; ++t) {          // k16 steps
            uint32_t bb[2][4][2];
            #pragma unroll
            for (int split = 0; split < 2; ++split)
                #pragma unroll
                for (int nt = 0; nt < 4; ++nt) {
                    const __nv_bfloat16* p =
                        pb + split * 65536 + nt * 8 * HD + t * 16;
                    bb[split][nt][0] = *(const uint32_t*)(p);
                    bb[split][nt][1] = *(const uint32_t*)(p + 8);
                }
            #pragma unroll
            for (int mt = 0; mt < 4; ++mt) {
                int row = (mg << 6) + (mt << 4) + (lid & 15);
                uint32_t aa = smb + A_OFF + row * AROW +
                              (t * 16 + ((lid >> 4) << 3)) * 2;
                uint32_t ah[4], al[4];
                ldsm4(ah, aa);
                ldsm4(al, aa + 528);
                #pragma unroll
                for (int nt = 0; nt < 4; ++nt) {
                    mma_bf16(acc[mt][nt], ah, bb[0][nt]);  // hi*hi
                    mma_bf16(acc[mt][nt], al, bb[0][nt]);  // lo*hi
                    mma_bf16(acc[mt][nt], ah, bb[1][nt]);  // hi*lo
                }
            }
        }
        HBAR(hh);   // all own-half MMA reads of A done before D overwrites A

        // ---- stage acc into D (aliases dead A rows of own half) -------------
        #pragma unroll
        for (int mt = 0; mt < 4; ++mt)
            #pragma unroll
            for (int nt = 0; nt < 4; ++nt) {
                int m0 = (mg << 6) + (mt << 4), nc = n0w + (nt << 3) + cc;
                *(float2*)(Dst + (m0 + g) * DROW + nc) =
                    make_float2(acc[mt][nt][0], acc[mt][nt][1]);
                *(float2*)(Dst + (m0 + g + 8) * DROW + nc) =
                    make_float2(acc[mt][nt][2], acc[mt][nt][3]);
            }
        HBAR(hh);

        // ---- activation epilogue (half-local) -------------------------------
        if (L == 0) {
            float bn = b2[nn];
            #pragma unroll 1
            for (int bb2 = 0; bb2 < 3; ++bb2) {
                float t5[4][5];
                #pragma unroll
                for (int j = 0; j < 4; ++j) {
                    int mr = hh * 64 + (bb2 * 4 + j) * 5;
                    #pragma unroll
                    for (int c = 0; c < 5; ++c)
                        t5[j][c] = Dst[(mr + c) * DROW + nn];
                }
                HBAR(hh);                   // all reads of these rows done
                #pragma unroll
                for (int j = 0; j < 4; ++j) {
                    int mr = hh * 64 + (bb2 * 4 + j) * 5;
                    float yv = ftanh(t5[j][0] + bn);
                    float sgm = fmaf(-yv, yv, 1.0f);
                    float gq = CX * t5[j][1] * t5[j][1] +
                               CY * t5[j][2] * t5[j][2] +
                               CZ * t5[j][3] * t5[j][3];
                    storeA(mr + 0, nn, yv);
                    storeA(mr + 1, nn, sgm * t5[j][1]);
                    storeA(mr + 2, nn, sgm * t5[j][2]);
                    storeA(mr + 3, nn, sgm * t5[j][3]);
                    storeA(mr + 4, nn, fmaf(sgm, t5[j][4],
                                            -2.0f * yv * sgm * gq));
                }
            }
            HBAR(hh);
        } else {
            float bn  = b3[nn];
            float w40 = W4[nn], w41 = W4[HD + nn];
            #pragma unroll 1
            for (int sl = 0; sl < 12; ++sl) {
                int s = hh * 12 + sl, mr = hh * 64 + sl * 5;
                float u  = Dst[(mr + 0) * DROW + nn] + bn;
                float tx = Dst[(mr + 1) * DROW + nn];
                float ty = Dst[(mr + 2) * DROW + nn];
                float tz = Dst[(mr + 3) * DROW + nn];
                float qa = Dst[(mr + 4) * DROW + nn];
                float yv = ftanh(u);
                float sgm = fmaf(-yv, yv, 1.0f);
                float gq = CX * tx * tx + CY * ty * ty + CZ * tz * tz;
                float qn = fmaf(sgm, qa, -2.0f * yv * sgm * gq);
                float v0 = w40 * yv, v1 = w41 * yv;
                float v2 = w40 * qn, v3 = w41 * qn;
                #pragma unroll
                for (int o = 16; o; o >>= 1) {
                    v0 += __shfl_xor_sync(0xFFFFFFFFu, v0, o);
                    v1 += __shfl_xor_sync(0xFFFFFFFFu, v1, o);
                    v2 += __shfl_xor_sync(0xFFFFFFFFu, v2, o);
                    v3 += __shfl_xor_sync(0xFFFFFFFFu, v3, o);
                }
                if (lid == 0) {
                    float* pp = part + (s * 8 + ng) * 4;
                    pp[0] = v0; pp[1] = v1; pp[2] = v2; pp[3] = v3;
                }
            }
        }
    }

    // ---- residual output (needs both halves) ---------------------------------
    __syncthreads();
    if (tid < SB) {
        int n = n0 + tid;
        if (n < N) {
            float P0 = 0.f, P1 = 0.f, Q0 = 0.f, Q1 = 0.f;
            #pragma unroll
            for (int w = 0; w < 8; ++w) {
                const float* pp = part + (tid * 8 + w) * 4;
                P0 += pp[0]; P1 += pp[1]; Q0 += pp[2]; Q1 += pp[3];
            }
            P0 += b4[0]; P1 += b4[1];
            float fs = xyzf[tid * 4 + 3];
            float kw = 6.283185307179586f * fmaf(fs, 500.0f, 100.0f) / 343.0f;
            float kx = 0.21f * kw;
            float K2 = kx * kx;
            out[n]     = 2.0f * Q0 + K2 * fmaf(2.0f, P0, 0.1f);
            out[N + n] = 1.5f * Q1 + K2 * fmaf(1.5f, P1, -0.05f);
        }
    }
}

extern "C" void kernel_launch(void* const* d_in, const int* in_sizes, int n_in,
                              void* d_out, int out_size)
{
    const float* x  = (const float*)d_in[0];
    const float* y  = (const float*)d_in[1];
    const float* z  = (const float*)d_in[2];
    const float* f  = (const float*)d_in[3];
    const float* W1 = (const float*)d_in[4];
    const float* b1 = (const float*)d_in[5];
    const float* W2 = (const float*)d_in[6];
    const float* b2 = (const float*)d_in[7];
    const float* W3 = (const float*)d_in[8];
    const float* b3 = (const float*)d_in[9];
    const float* W4 = (const float*)d_in[10];
    const float* b4 = (const float*)d_in[11];
    float* out = (float*)d_out;

    int N = in_sizes[0];
    prep_weights<<<512, 256>>>(W2, W3);

    cudaFuncSetAttribute(bvp_mma_kernel,
                         cudaFuncAttributeMaxDynamicSharedMemorySize,
                         SMEM_BYTES);
    int blocks = (N + SB - 1) / SB;
    bvp_mma_kernel<<<blocks, 512, SMEM_BYTES>>>(x, y, z, f, W1, b1, b2, b3,
                                                W4, b4, out, N);
}

// round 12
// speedup vs baseline: 1.2644x; 1.2644x over previous
#include <cuda_runtime.h>
#include <cuda_bf16.h>
#include <cstdint>

// ---------------------------------------------------------------------------
// BVP Helmholtz residual via 2nd-order jet propagation on mma.sync bf16 HMMA
// (3-pass hi/lo split). Round 12: PER-WARP private B pipelines — each warp
// owns a double-buffered 32-row B slice (k16 chunks, hi/lo interleaved,
// 80B rows) filled by its own cp.async stream with per-warp wait_group.
// ZERO barriers / cross-warp coupling in the mainloop; warps drift freely.
// CTA split into two independent 256-thread halves for all epilogues
// (named barriers); A aliased by D row-for-row as before.
// ---------------------------------------------------------------------------

#define HD 256
#define SB 24             // samples per CTA (12 per half)
#define AROW 1040         // A row bytes: hi[0,512) pad lo[528,1040) == D row
#define DROW 260          // D row stride in floats (= 1040 B)
#define BROW 80           // B slice row: hi k16 (32B) + lo k16 (32B) + pad
#define BSTG 2560         // 32 rows * 80 = one stage of one warp's slice
#define BTOT 5120         // 2 stages

#define A_OFF 0
#define B_OFF 133120      // 128*1040
#define XYZF_OFF 215040   // B region = 16 warps * 5120 = 81920
#define PART_OFF 215424
#define SMEM_BYTES 218624

// prepped weights: [layer][split hi/lo][n][k] bf16
__device__ __align__(16) __nv_bfloat16 Wbf[2][2][HD][HD];

__global__ __launch_bounds__(256)
void prep_weights(const float* __restrict__ W2, const float* __restrict__ W3)
{
    int t = blockIdx.x * 256 + threadIdx.x;      // 131072
    int layer = t >> 16, n = (t >> 8) & 255, k = t & 255;
    float w = (layer ? W3 : W2)[n * HD + k];
    __nv_bfloat16 h = __float2bfloat16(w);
    __nv_bfloat16 l = __float2bfloat16(w - __bfloat162float(h));
    Wbf[layer][0][n][k] = h;
    Wbf[layer][1][n][k] = l;
}

__device__ __forceinline__ uint32_t smem_u32(const void* p) {
    uint32_t a;
    asm("{ .reg .u64 t; cvta.to.shared.u64 t, %1; cvt.u32.u64 %0, t; }"
        : "=r"(a) : "l"(p));
    return a;
}
__device__ __forceinline__ void ldsm4(uint32_t* r, uint32_t a) {
    asm volatile("ldmatrix.sync.aligned.m8n8.x4.shared.b16 {%0,%1,%2,%3}, [%4];"
                 : "=r"(r[0]), "=r"(r[1]), "=r"(r[2]), "=r"(r[3]) : "r"(a));
}
__device__ __forceinline__ void ldsm2(uint32_t* r, uint32_t a) {
    asm volatile("ldmatrix.sync.aligned.m8n8.x2.shared.b16 {%0,%1}, [%2];"
                 : "=r"(r[0]), "=r"(r[1]) : "r"(a));
}
__device__ __forceinline__ void mma_bf16(float* c, const uint32_t* a,
                                         const uint32_t* b) {
    asm volatile("mma.sync.aligned.m16n8k16.row.col.f32.bf16.bf16.f32 "
                 "{%0,%1,%2,%3}, {%4,%5,%6,%7}, {%8,%9}, {%0,%1,%2,%3};"
                 : "+f"(c[0]), "+f"(c[1]), "+f"(c[2]), "+f"(c[3])
                 : "r"(a[0]), "r"(a[1]), "r"(a[2]), "r"(a[3]),
                   "r"(b[0]), "r"(b[1]));
}
__device__ __forceinline__ void cp16(uint32_t sa, const void* ga) {
    asm volatile("cp.async.cg.shared.global [%0], [%1], 16;"
                 :: "r"(sa), "l"(__cvta_generic_to_global(ga)) : "memory");
}
#define CP_COMMIT() asm volatile("cp.async.commit_group;" ::: "memory")
#define CP_WAIT(n)  asm volatile("cp.async.wait_group %0;" :: "n"(n) : "memory")
// per-half named barrier (256 threads each); ids 1,2
#define HBAR(h) asm volatile("bar.sync %0, 256;" :: "r"((h) + 1) : "memory")

// fast tanh: 1 - 2/(exp(2u)+1). abs err ~3e-7.
__device__ __forceinline__ float ftanh(float u) {
    float e = __expf(2.0f * u);
    return 1.0f - __fdividef(2.0f, e + 1.0f);
}

__global__ __launch_bounds__(512, 1)
void bvp_mma_kernel(const float* __restrict__ gx, const float* __restrict__ gy,
                    const float* __restrict__ gz, const float* __restrict__ gf,
                    const float* __restrict__ W1, const float* __restrict__ b1,
                    const float* __restrict__ b2, const float* __restrict__ b3,
                    const float* __restrict__ W4, const float* __restrict__ b4,
                    float* __restrict__ out, int N)
{
    extern __shared__ char sm[];
    const uint32_t smb = smem_u32(sm);
    float* Dst  = (float*)(sm + A_OFF);       // aliases A region, row-for-row
    float* xyzf = (float*)(sm + XYZF_OFF);
    float* part = (float*)(sm + PART_OFF);    // [24][8][4]

    const int tid = threadIdx.x;
    const int wid = tid >> 5;
    const int lid = tid & 31;
    const int mg  = wid >> 3;                 // half (rows mg*64..+64)
    const int ng  = wid & 7;                  // n-slice (cols ng*32..+32)
    const int n0w = ng << 5;
    const int n0  = blockIdx.x * SB;
    const int hh  = tid >> 8;                 // == mg
    const int nn  = tid & 255;

    const float CX = (float)((0.5 * 0.6) * (0.5 * 0.6));
    const float CY = (float)((0.7 * 0.6) * (0.7 * 0.6));
    const float CZ = (float)((0.7 * 0.5) * (0.7 * 0.5));

    // warp-private B slice (double buffered), filled by this warp only.
    const uint32_t myb = smb + B_OFF + wid * BTOT;
    auto issue_chunk = [&](int gi) {          // gi in [0,32): layer*16 + kc
        int L = gi >> 4, kc = gi & 15;
        uint32_t base = myb + (gi & 1) * BSTG;
        #pragma unroll
        for (int j = 0; j < 4; ++j) {
            int idx = lid + (j << 5);         // 0..127
            int r = idx >> 2, q = idx & 3;
            int split = q >> 1, half = q & 1;
            cp16(base + r * BROW + split * 32 + half * 16,
                 &Wbf[L][split][n0w + r][kc * 16 + half * 8]);
        }
        CP_COMMIT();
    };

    auto storeA = [&](int m, int k, float v) {
        __nv_bfloat16 h = __float2bfloat16(v);
        __nv_bfloat16 l = __float2bfloat16(v - __bfloat162float(h));
        char* base = sm + A_OFF + m * AROW + k * 2;
        *(__nv_bfloat16*)(base)       = h;
        *(__nv_bfloat16*)(base + 528) = l;
    };

    // prologue: prefetch chunks 0,1 of layer 0 (per warp, private)
    issue_chunk(0);
    issue_chunk(1);

    // coords (full CTA, one full sync)
    if (tid < 96) {
        int ss = tid >> 2, w = tid & 3;
        int n = n0 + ss; if (n >= N) n = N - 1;
        const float* p = (w == 0) ? gx : (w == 1) ? gy : (w == 2) ? gz : gf;
        xyzf[tid] = p[n];
    }
    __syncthreads();

    // ---- layer 1: 4 -> 256, jets analytically (half-local) -----------------
    {
        float4 w = *(const float4*)(W1 + nn * 4);
        float bb = b1[nn];
        float g  = CX * w.x * w.x + CY * w.y * w.y + CZ * w.z * w.z;
        #pragma unroll 1
        for (int sl = 0; sl < 12; ++sl) {
            int s = hh * 12 + sl;
            float u = fmaf(w.x, xyzf[s * 4 + 0], fmaf(w.y, xyzf[s * 4 + 1],
                      fmaf(w.z, xyzf[s * 4 + 2], fmaf(w.w, xyzf[s * 4 + 3],
                      bb))));
            float yv = ftanh(u);
            float sg = fmaf(-yv, yv, 1.0f);
            int m = hh * 64 + sl * 5;
            storeA(m + 0, nn, yv);
            storeA(m + 1, nn, sg * w.x);
            storeA(m + 2, nn, sg * w.y);
            storeA(m + 3, nn, sg * w.z);
            storeA(m + 4, nn, -2.0f * yv * sg * g);
        }
    }
    HBAR(hh);

    const int g = lid >> 2, cc = (lid & 3) << 1;

    // ---- hidden layers 2,3 (zero-sync mainloop) -----------------------------
    #pragma unroll 1
    for (int L = 0; L < 2; ++L) {
        float acc[4][4][4];
        #pragma unroll
        for (int mt = 0; mt < 4; ++mt)
            #pragma unroll
            for (int nt = 0; nt < 4; ++nt)
                #pragma unroll
                for (int r = 0; r < 4; ++r) acc[mt][nt][r] = 0.f;

        #pragma unroll 1
        for (int kc = 0; kc < 16; ++kc) {     // k16 chunks
            int gi = (L << 4) | kc;
            if (gi == 31) { CP_WAIT(0); } else { CP_WAIT(1); }
            uint32_t bbase = myb + (gi & 1) * BSTG;

            uint32_t bh[4][2], bl[4][2];
            #pragma unroll
            for (int nt = 0; nt < 4; ++nt) {
                uint32_t ba = bbase + ((nt << 3) + (lid & 7)) * BROW +
                              (lid & 8) * 2;
                ldsm2(bh[nt], ba);
                ldsm2(bl[nt], ba + 32);
            }
            #pragma unroll
            for (int mt = 0; mt < 4; ++mt) {
                int row = (mg << 6) + (mt << 4) + (lid & 15);
                uint32_t aa = smb + A_OFF + row * AROW +
                              (kc * 16 + ((lid >> 4) << 3)) * 2;
                uint32_t ah[4], al[4];
                ldsm4(ah, aa);
                ldsm4(al, aa + 528);
                #pragma unroll
                for (int nt = 0; nt < 4; ++nt) {
                    mma_bf16(acc[mt][nt], ah, bh[nt]);  // hi*hi
                    mma_bf16(acc[mt][nt], al, bh[nt]);  // lo*hi
                    mma_bf16(acc[mt][nt], ah, bl[nt]);  // hi*lo
                }
            }
            // refill the buffer this chunk just finished reading (private)
            if (gi + 2 < 32) issue_chunk(gi + 2);
        }
        HBAR(hh);   // all own-half MMA reads of A done before D overwrites A

        // ---- stage acc into D (aliases dead A rows of own half) -------------
        #pragma unroll
        for (int mt = 0; mt < 4; ++mt)
            #pragma unroll
            for (int nt = 0; nt < 4; ++nt) {
                int m0 = (mg << 6) + (mt << 4), nc = n0w + (nt << 3) + cc;
                *(float2*)(Dst + (m0 + g) * DROW + nc) =
                    make_float2(acc[mt][nt][0], acc[mt][nt][1]);
                *(float2*)(Dst + (m0 + g + 8) * DROW + nc) =
                    make_float2(acc[mt][nt][2], acc[mt][nt][3]);
            }
        HBAR(hh);

        // ---- activation epilogue (half-local) -------------------------------
        if (L == 0) {
            float bn = b2[nn];
            #pragma unroll 1
            for (int bb2 = 0; bb2 < 3; ++bb2) {
                float t5[4][5];
                #pragma unroll
                for (int j = 0; j < 4; ++j) {
                    int mr = hh * 64 + (bb2 * 4 + j) * 5;
                    #pragma unroll
                    for (int c = 0; c < 5; ++c)
                        t5[j][c] = Dst[(mr + c) * DROW + nn];
                }
                HBAR(hh);                   // all reads of these rows done
                #pragma unroll
                for (int j = 0; j < 4; ++j) {
                    int mr = hh * 64 + (bb2 * 4 + j) * 5;
                    float yv = ftanh(t5[j][0] + bn);
                    float sgm = fmaf(-yv, yv, 1.0f);
                    float gq = CX * t5[j][1] * t5[j][1] +
                               CY * t5[j][2] * t5[j][2] +
                               CZ * t5[j][3] * t5[j][3];
                    storeA(mr + 0, nn, yv);
                    storeA(mr + 1, nn, sgm * t5[j][1]);
                    storeA(mr + 2, nn, sgm * t5[j][2]);
                    storeA(mr + 3, nn, sgm * t5[j][3]);
                    storeA(mr + 4, nn, fmaf(sgm, t5[j][4],
                                            -2.0f * yv * sgm * gq));
                }
            }
            HBAR(hh);
        } else {
            float bn  = b3[nn];
            float w40 = W4[nn], w41 = W4[HD + nn];
            #pragma unroll 1
            for (int sl = 0; sl < 12; ++sl) {
                int s = hh * 12 + sl, mr = hh * 64 + sl * 5;
                float u  = Dst[(mr + 0) * DROW + nn] + bn;
                float tx = Dst[(mr + 1) * DROW + nn];
                float ty = Dst[(mr + 2) * DROW + nn];
                float tz = Dst[(mr + 3) * DROW + nn];
                float qa = Dst[(mr + 4) * DROW + nn];
                float yv = ftanh(u);
                float sgm = fmaf(-yv, yv, 1.0f);
                float gq = CX * tx * tx + CY * ty * ty + CZ * tz * tz;
                float qn = fmaf(sgm, qa, -2.0f * yv * sgm * gq);
                float v0 = w40 * yv, v1 = w41 * yv;
                float v2 = w40 * qn, v3 = w41 * qn;
                #pragma unroll
                for (int o = 16; o; o >>= 1) {
                    v0 += __shfl_xor_sync(0xFFFFFFFFu, v0, o);
                    v1 += __shfl_xor_sync(0xFFFFFFFFu, v1, o);
                    v2 += __shfl_xor_sync(0xFFFFFFFFu, v2, o);
                    v3 += __shfl_xor_sync(0xFFFFFFFFu, v3, o);
                }
                if (lid == 0) {
                    float* pp = part + (s * 8 + ng) * 4;
                    pp[0] = v0; pp[1] = v1; pp[2] = v2; pp[3] = v3;
                }
            }
        }
    }

    // ---- residual output (needs both halves) ---------------------------------
    __syncthreads();
    if (tid < SB) {
        int n = n0 + tid;
        if (n < N) {
            float P0 = 0.f, P1 = 0.f, Q0 = 0.f, Q1 = 0.f;
            #pragma unroll
            for (int w = 0; w < 8; ++w) {
                const float* pp = part + (tid * 8 + w) * 4;
                P0 += pp[0]; P1 += pp[1]; Q0 += pp[2]; Q1 += pp[3];
            }
            P0 += b4[0]; P1 += b4[1];
            float fs = xyzf[tid * 4 + 3];
            float kw = 6.283185307179586f * fmaf(fs, 500.0f, 100.0f) / 343.0f;
            float kx = 0.21f * kw;
            float K2 = kx * kx;
            out[n]     = 2.0f * Q0 + K2 * fmaf(2.0f, P0, 0.1f);
            out[N + n] = 1.5f * Q1 + K2 * fmaf(1.5f, P1, -0.05f);
        }
    }
}

extern "C" void kernel_launch(void* const* d_in, const int* in_sizes, int n_in,
                              void* d_out, int out_size)
{
    const float* x  = (const float*)d_in[0];
    const float* y  = (const float*)d_in[1];
    const float* z  = (const float*)d_in[2];
    const float* f  = (const float*)d_in[3];
    const float* W1 = (const float*)d_in[4];
    const float* b1 = (const float*)d_in[5];
    const float* W2 = (const float*)d_in[6];
    const float* b2 = (const float*)d_in[7];
    const float* W3 = (const float*)d_in[8];
    const float* b3 = (const float*)d_in[9];
    const float* W4 = (const float*)d_in[10];
    const float* b4 = (const float*)d_in[11];
    float* out = (float*)d_out;

    int N = in_sizes[0];
    prep_weights<<<512, 256>>>(W2, W3);

    cudaFuncSetAttribute(bvp_mma_kernel,
                         cudaFuncAttributeMaxDynamicSharedMemorySize,
                         SMEM_BYTES);
    int blocks = (N + SB - 1) / SB;
    bvp_mma_kernel<<<blocks, 512, SMEM_BYTES>>>(x, y, z, f, W1, b1, b2, b3,
                                                W4, b4, out, N);
}

// round 13
// speedup vs baseline: 1.3470x; 1.0653x over previous
#include <cuda_runtime.h>
#include <cuda_bf16.h>
#include <cstdint>

// ---------------------------------------------------------------------------
// BVP Helmholtz residual via 2nd-order jet propagation on mma.sync bf16 HMMA
// (3-pass hi/lo split). Round 13: 256 threads, M=64 (12 samples/CTA), 8 warps
// each with a PRIVATE double-buffered B pipeline (k16 chunks, cp.async,
// per-warp wait_group) -> zero mainloop barriers; smem 109.3KB -> 2 CTAs/SM
// so one CTA's epilogue/convergence phases overlap the other's MMA mainloop.
// D staging aliases dead A rows (in-place jet exchange).
// ---------------------------------------------------------------------------

#define HD 256
#define SB 12             // samples per CTA
#define AROW 1040         // A row bytes: hi[0,512) pad lo[528,1040) == D row
#define DROW 260          // D row stride in floats (= 1040 B)
#define BROW 80           // B slice row: hi k16 (32B) + lo k16 (32B) + pad
#define BSTG 2560         // 32 rows * 80 = one stage of one warp's slice
#define BTOT 5120         // 2 stages

#define A_OFF 0
#define B_OFF 66560       // 64*1040
#define XYZF_OFF 107520   // B region = 8 warps * 5120 = 40960
#define PART_OFF 107776
#define SMEM_BYTES 109312

// prepped weights: [layer][split hi/lo][n][k] bf16
__device__ __align__(16) __nv_bfloat16 Wbf[2][2][HD][HD];

__global__ __launch_bounds__(256)
void prep_weights(const float* __restrict__ W2, const float* __restrict__ W3)
{
    int t = blockIdx.x * 256 + threadIdx.x;      // 131072
    int layer = t >> 16, n = (t >> 8) & 255, k = t & 255;
    float w = (layer ? W3 : W2)[n * HD + k];
    __nv_bfloat16 h = __float2bfloat16(w);
    __nv_bfloat16 l = __float2bfloat16(w - __bfloat162float(h));
    Wbf[layer][0][n][k] = h;
    Wbf[layer][1][n][k] = l;
}

__device__ __forceinline__ uint32_t smem_u32(const void* p) {
    uint32_t a;
    asm("{ .reg .u64 t; cvta.to.shared.u64 t, %1; cvt.u32.u64 %0, t; }"
        : "=r"(a) : "l"(p));
    return a;
}
__device__ __forceinline__ void ldsm4(uint32_t* r, uint32_t a) {
    asm volatile("ldmatrix.sync.aligned.m8n8.x4.shared.b16 {%0,%1,%2,%3}, [%4];"
                 : "=r"(r[0]), "=r"(r[1]), "=r"(r[2]), "=r"(r[3]) : "r"(a));
}
__device__ __forceinline__ void ldsm2(uint32_t* r, uint32_t a) {
    asm volatile("ldmatrix.sync.aligned.m8n8.x2.shared.b16 {%0,%1}, [%2];"
                 : "=r"(r[0]), "=r"(r[1]) : "r"(a));
}
__device__ __forceinline__ void mma_bf16(float* c, const uint32_t* a,
                                         const uint32_t* b) {
    asm volatile("mma.sync.aligned.m16n8k16.row.col.f32.bf16.bf16.f32 "
                 "{%0,%1,%2,%3}, {%4,%5,%6,%7}, {%8,%9}, {%0,%1,%2,%3};"
                 : "+f"(c[0]), "+f"(c[1]), "+f"(c[2]), "+f"(c[3])
                 : "r"(a[0]), "r"(a[1]), "r"(a[2]), "r"(a[3]),
                   "r"(b[0]), "r"(b[1]));
}
__device__ __forceinline__ void cp16(uint32_t sa, const void* ga) {
    asm volatile("cp.async.cg.shared.global [%0], [%1], 16;"
                 :: "r"(sa), "l"(__cvta_generic_to_global(ga)) : "memory");
}
#define CP_COMMIT() asm volatile("cp.async.commit_group;" ::: "memory")
#define CP_WAIT(n)  asm volatile("cp.async.wait_group %0;" :: "n"(n) : "memory")

// fast tanh: 1 - 2/(exp(2u)+1). abs err ~3e-7.
__device__ __forceinline__ float ftanh(float u) {
    float e = __expf(2.0f * u);
    return 1.0f - __fdividef(2.0f, e + 1.0f);
}

__global__ __launch_bounds__(256, 2)
void bvp_mma_kernel(const float* __restrict__ gx, const float* __restrict__ gy,
                    const float* __restrict__ gz, const float* __restrict__ gf,
                    const float* __restrict__ W1, const float* __restrict__ b1,
                    const float* __restrict__ b2, const float* __restrict__ b3,
                    const float* __restrict__ W4, const float* __restrict__ b4,
                    float* __restrict__ out, int N)
{
    extern __shared__ char sm[];
    const uint32_t smb = smem_u32(sm);
    float* Dst  = (float*)(sm + A_OFF);       // aliases A region, row-for-row
    float* xyzf = (float*)(sm + XYZF_OFF);
    float* part = (float*)(sm + PART_OFF);    // [12][8][4]

    const int tid = threadIdx.x;
    const int wid = tid >> 5;                 // n-slice (cols wid*32..+32)
    const int lid = tid & 31;
    const int n0w = wid << 5;
    const int n0  = blockIdx.x * SB;

    const float CX = (float)((0.5 * 0.6) * (0.5 * 0.6));
    const float CY = (float)((0.7 * 0.6) * (0.7 * 0.6));
    const float CZ = (float)((0.7 * 0.5) * (0.7 * 0.5));

    // warp-private B slice (double buffered), filled by this warp only.
    const uint32_t myb = smb + B_OFF + wid * BTOT;
    auto issue_chunk = [&](int gi) {          // gi in [0,32): layer*16 + kc
        int L = gi >> 4, kc = gi & 15;
        uint32_t base = myb + (gi & 1) * BSTG;
        #pragma unroll
        for (int j = 0; j < 4; ++j) {
            int idx = lid + (j << 5);         // 0..127
            int r = idx >> 2, q = idx & 3;
            int split = q >> 1, half = q & 1;
            cp16(base + r * BROW + split * 32 + half * 16,
                 &Wbf[L][split][n0w + r][kc * 16 + half * 8]);
        }
        CP_COMMIT();
    };

    auto storeA = [&](int m, int k, float v) {
        __nv_bfloat16 h = __float2bfloat16(v);
        __nv_bfloat16 l = __float2bfloat16(v - __bfloat162float(h));
        char* base = sm + A_OFF + m * AROW + k * 2;
        *(__nv_bfloat16*)(base)       = h;
        *(__nv_bfloat16*)(base + 528) = l;
    };

    // prologue: prefetch chunks 0,1 of layer 0 (per warp, private)
    issue_chunk(0);
    issue_chunk(1);

    // coords
    if (tid < 48) {
        int ss = tid >> 2, w = tid & 3;
        int n = n0 + ss; if (n >= N) n = N - 1;
        const float* p = (w == 0) ? gx : (w == 1) ? gy : (w == 2) ? gz : gf;
        xyzf[tid] = p[n];
    }
    __syncthreads();

    // ---- layer 1: 4 -> 256, jets analytically ------------------------------
    {
        float4 w = *(const float4*)(W1 + tid * 4);
        float bb = b1[tid];
        float g  = CX * w.x * w.x + CY * w.y * w.y + CZ * w.z * w.z;
        #pragma unroll 1
        for (int s = 0; s < SB; ++s) {
            float u = fmaf(w.x, xyzf[s * 4 + 0], fmaf(w.y, xyzf[s * 4 + 1],
                      fmaf(w.z, xyzf[s * 4 + 2], fmaf(w.w, xyzf[s * 4 + 3],
                      bb))));
            float yv = ftanh(u);
            float sg = fmaf(-yv, yv, 1.0f);
            int m = s * 5;
            storeA(m + 0, tid, yv);
            storeA(m + 1, tid, sg * w.x);
            storeA(m + 2, tid, sg * w.y);
            storeA(m + 3, tid, sg * w.z);
            storeA(m + 4, tid, -2.0f * yv * sg * g);
        }
        // zero pad rows 60..63 (both splits)
        storeA(60 + (tid >> 8), tid & 255, 0.0f);
        storeA(61, tid, 0.0f);
        storeA(62, tid, 0.0f);
        storeA(63, tid, 0.0f);
        storeA(60, tid, 0.0f);
    }
    __syncthreads();

    const int g = lid >> 2, cc = (lid & 3) << 1;

    // ---- hidden layers 2,3 (zero-sync mainloop) -----------------------------
    #pragma unroll 1
    for (int L = 0; L < 2; ++L) {
        float acc[4][4][4];
        #pragma unroll
        for (int mt = 0; mt < 4; ++mt)
            #pragma unroll
            for (int nt = 0; nt < 4; ++nt)
                #pragma unroll
                for (int r = 0; r < 4; ++r) acc[mt][nt][r] = 0.f;

        #pragma unroll 1
        for (int kc = 0; kc < 16; ++kc) {     // k16 chunks
            int gi = (L << 4) | kc;
            if (gi == 31) { CP_WAIT(0); } else { CP_WAIT(1); }
            uint32_t bbase = myb + (gi & 1) * BSTG;

            uint32_t bh[4][2], bl[4][2];
            #pragma unroll
            for (int nt = 0; nt < 4; ++nt) {
                uint32_t ba = bbase + ((nt << 3) + (lid & 7)) * BROW +
                              (lid & 8) * 2;
                ldsm2(bh[nt], ba);
                ldsm2(bl[nt], ba + 32);
            }
            #pragma unroll
            for (int mt = 0; mt < 4; ++mt) {
                int row = (mt << 4) + (lid & 15);
                uint32_t aa = smb + A_OFF + row * AROW +
                              (kc * 16 + ((lid >> 4) << 3)) * 2;
                uint32_t ah[4], al[4];
                ldsm4(ah, aa);
                ldsm4(al, aa + 528);
                #pragma unroll
                for (int nt = 0; nt < 4; ++nt) {
                    mma_bf16(acc[mt][nt], ah, bh[nt]);  // hi*hi
                    mma_bf16(acc[mt][nt], al, bh[nt]);  // lo*hi
                    mma_bf16(acc[mt][nt], ah, bl[nt]);  // hi*lo
                }
            }
            // refill the buffer this chunk just finished reading (private)
            if (gi + 2 < 32) issue_chunk(gi + 2);
        }
        __syncthreads();   // all MMA reads of A done before D overwrites A

        // ---- stage acc into D (aliases dead A rows) --------------------------
        #pragma unroll
        for (int mt = 0; mt < 4; ++mt)
            #pragma unroll
            for (int nt = 0; nt < 4; ++nt) {
                int m0 = (mt << 4), nc = n0w + (nt << 3) + cc;
                *(float2*)(Dst + (m0 + g) * DROW + nc) =
                    make_float2(acc[mt][nt][0], acc[mt][nt][1]);
                *(float2*)(Dst + (m0 + g + 8) * DROW + nc) =
                    make_float2(acc[mt][nt][2], acc[mt][nt][3]);
            }
        __syncthreads();

        // ---- activation epilogue --------------------------------------------
        if (L == 0) {
            // in-place D -> new A exchange, batched 4 samples per barrier
            float bn = b2[tid];
            #pragma unroll 1
            for (int bb2 = 0; bb2 < 3; ++bb2) {
                float t5[4][5];
                #pragma unroll
                for (int j = 0; j < 4; ++j) {
                    int mr = (bb2 * 4 + j) * 5;
                    #pragma unroll
                    for (int c = 0; c < 5; ++c)
                        t5[j][c] = Dst[(mr + c) * DROW + tid];
                }
                __syncthreads();           // all reads of these rows done
                #pragma unroll
                for (int j = 0; j < 4; ++j) {
                    int mr = (bb2 * 4 + j) * 5;
                    float yv = ftanh(t5[j][0] + bn);
                    float sgm = fmaf(-yv, yv, 1.0f);
                    float gq = CX * t5[j][1] * t5[j][1] +
                               CY * t5[j][2] * t5[j][2] +
                               CZ * t5[j][3] * t5[j][3];
                    storeA(mr + 0, tid, yv);
                    storeA(mr + 1, tid, sgm * t5[j][1]);
                    storeA(mr + 2, tid, sgm * t5[j][2]);
                    storeA(mr + 3, tid, sgm * t5[j][3]);
                    storeA(mr + 4, tid, fmaf(sgm, t5[j][4],
                                             -2.0f * yv * sgm * gq));
                }
            }
            __syncthreads();
        } else {
            float bn  = b3[tid];
            float w40 = W4[tid], w41 = W4[HD + tid];
            #pragma unroll 1
            for (int s = 0; s < SB; ++s) {
                int mr = s * 5;
                float u  = Dst[(mr + 0) * DROW + tid] + bn;
                float tx = Dst[(mr + 1) * DROW + tid];
                float ty = Dst[(mr + 2) * DROW + tid];
                float tz = Dst[(mr + 3) * DROW + tid];
                float qa = Dst[(mr + 4) * DROW + tid];
                float yv = ftanh(u);
                float sgm = fmaf(-yv, yv, 1.0f);
                float gq = CX * tx * tx + CY * ty * ty + CZ * tz * tz;
                float qn = fmaf(sgm, qa, -2.0f * yv * sgm * gq);
                float v0 = w40 * yv, v1 = w41 * yv;
                float v2 = w40 * qn, v3 = w41 * qn;
                #pragma unroll
                for (int o = 16; o; o >>= 1) {
                    v0 += __shfl_xor_sync(0xFFFFFFFFu, v0, o);
                    v1 += __shfl_xor_sync(0xFFFFFFFFu, v1, o);
                    v2 += __shfl_xor_sync(0xFFFFFFFFu, v2, o);
                    v3 += __shfl_xor_sync(0xFFFFFFFFu, v3, o);
                }
                if (lid == 0) {
                    float* pp = part + (s * 8 + wid) * 4;
                    pp[0] = v0; pp[1] = v1; pp[2] = v2; pp[3] = v3;
                }
            }
            __syncthreads();
        }
    }

    // ---- residual output -----------------------------------------------------
    if (tid < SB) {
        int n = n0 + tid;
        if (n < N) {
            float P0 = 0.f, P1 = 0.f, Q0 = 0.f, Q1 = 0.f;
            #pragma unroll
            for (int w = 0; w < 8; ++w) {
                const float* pp = part + (tid * 8 + w) * 4;
                P0 += pp[0]; P1 += pp[1]; Q0 += pp[2]; Q1 += pp[3];
            }
            P0 += b4[0]; P1 += b4[1];
            float fs = xyzf[tid * 4 + 3];
            float kw = 6.283185307179586f * fmaf(fs, 500.0f, 100.0f) / 343.0f;
            float kx = 0.21f * kw;
            float K2 = kx * kx;
            out[n]     = 2.0f * Q0 + K2 * fmaf(2.0f, P0, 0.1f);
            out[N + n] = 1.5f * Q1 + K2 * fmaf(1.5f, P1, -0.05f);
        }
    }
}

extern "C" void kernel_launch(void* const* d_in, const int* in_sizes, int n_in,
                              void* d_out, int out_size)
{
    const float* x  = (const float*)d_in[0];
    const float* y  = (const float*)d_in[1];
    const float* z  = (const float*)d_in[2];
    const float* f  = (const float*)d_in[3];
    const float* W1 = (const float*)d_in[4];
    const float* b1 = (const float*)d_in[5];
    const float* W2 = (const float*)d_in[6];
    const float* b2 = (const float*)d_in[7];
    const float* W3 = (const float*)d_in[8];
    const float* b3 = (const float*)d_in[9];
    const float* W4 = (const float*)d_in[10];
    const float* b4 = (const float*)d_in[11];
    float* out = (float*)d_out;

    int N = in_sizes[0];
    prep_weights<<<512, 256>>>(W2, W3);

    cudaFuncSetAttribute(bvp_mma_kernel,
                         cudaFuncAttributeMaxDynamicSharedMemorySize,
                         SMEM_BYTES);
    int blocks = (N + SB - 1) / SB;
    bvp_mma_kernel<<<blocks, 256, SMEM_BYTES>>>(x, y, z, f, W1, b1, b2, b3,
                                                W4, b4, out, N);
}